// round 5
// baseline (speedup 1.0000x reference)
#include <cuda_runtime.h>

#define BB 4
#define EE 1500
#define DD 256
#define HH 8
#define DK 32

#define O_ATTN 1536000
#define O_APE  73536000

typedef unsigned long long ull;

// ---------------- scratch (no allocation allowed) ----------------
__device__ float g_q[BB*HH*EE*DK];     // scaled q, [b,h,e,dk]
__device__ float g_k[BB*HH*EE*DK];
__device__ float g_v[BB*HH*EE*DK];
__device__ float g_qdr[BB*HH*EE*8];    // q . base_rpr[p], p padded to 8
__device__ float g_o[BB*EE*DD];        // attention output pre-FC, [b,e,h*32+d]
__device__ float g_asum[BB*EE];
__device__ int   g_acnt[BB*EE];

__device__ __forceinline__ float warp_sum(float v) {
    #pragma unroll
    for (int o = 16; o; o >>= 1) v += __shfl_xor_sync(0xffffffffu, v, o);
    return v;
}
__device__ __forceinline__ float warp_max(float v) {
    #pragma unroll
    for (int o = 16; o; o >>= 1) v = fmaxf(v, __shfl_xor_sync(0xffffffffu, v, o));
    return v;
}

// packed f32x2 helpers (sm_100+)
__device__ __forceinline__ void fma2(ull &d, ull a, ull b) {
    asm("fma.rn.f32x2 %0, %1, %2, %0;" : "+l"(d) : "l"(a), "l"(b));
}
__device__ __forceinline__ ull f2add(ull a, ull b) {
    ull d;
    asm("add.rn.f32x2 %0, %1, %2;" : "=l"(d) : "l"(a), "l"(b));
    return d;
}
__device__ __forceinline__ float f2sum(ull u) {
    float lo, hi;
    asm("mov.b64 {%0,%1}, %2;" : "=f"(lo), "=f"(hi) : "l"(u));
    return lo + hi;
}
__device__ __forceinline__ ull packf2(float x, float y) {
    ull u;
    asm("mov.b64 %0, {%1,%2};" : "=l"(u) : "f"(x), "f"(y));
    return u;
}

// ---------------- K0: zero accumulators ----------------
__global__ void zero_kernel() {
    int i = blockIdx.x * 256 + threadIdx.x;
    if (i < BB*EE) { g_asum[i] = 0.f; g_acnt[i] = 0; }
}

// ---------------- K0b: valid-edge counts from dist ----------------
__global__ void count_kernel(const int* __restrict__ dist) {
    int i = blockIdx.x * 256 + threadIdx.x;   // b*EE + e
    if (i >= BB*EE) return;
    int b = i / EE, e = i - b*EE;
    int q0 = blockIdx.y * 188;
    int q1 = min(EE, q0 + 188);
    const int* dp = dist + (long long)b*EE*EE + e;
    int c = 0;
    #pragma unroll 4
    for (int q = q0; q < q1; q++) c += (dp[q*EE] <= 3) ? 1 : 0;
    atomicAdd(&g_acnt[i], c);
}

// ---------------- K1: layernorm + QKV projections + q.rpr ----------------
__global__ void __launch_bounds__(256) proj_kernel(
    const float* __restrict__ x,
    const float* __restrict__ Wq, const float* __restrict__ Wk,
    const float* __restrict__ Wv,
    const float* __restrict__ lnw, const float* __restrict__ lnb,
    const float* __restrict__ rpr)
{
    __shared__ __align__(16) float ssm[256*8];   // [d][r] raw input rows
    __shared__ __align__(16) float nsm[256*8];   // [d][r] layernormed rows
    int b  = blockIdx.y;
    int e0 = blockIdx.x * 8;
    int t  = threadIdx.x;
    const float* xb = x + b*(DD*EE);

    for (int i = t; i < 2048; i += 256) {
        int d = i >> 3, r = i & 7;
        int e = e0 + r;
        ssm[i] = (e < EE) ? xb[d*EE + e] : 0.f;
    }
    __syncthreads();

    int w = t >> 5, lane = t & 31;
    {   // layernorm of row w (one row per warp)
        float s = 0.f;
        #pragma unroll
        for (int i = 0; i < 8; i++) s += ssm[(lane + 32*i)*8 + w];
        s = warp_sum(s);
        float mu = s * (1.f/256.f);
        float vs = 0.f;
        #pragma unroll
        for (int i = 0; i < 8; i++) {
            float dlt = ssm[(lane + 32*i)*8 + w] - mu;
            vs += dlt*dlt;
        }
        vs = warp_sum(vs);
        float rstd = rsqrtf(vs * (1.f/256.f) + 1e-6f);
        #pragma unroll
        for (int i = 0; i < 8; i++) {
            int d = lane + 32*i;
            nsm[d*8 + w] = (ssm[d*8 + w] - mu) * rstd * lnw[d] + lnb[d];
        }
    }
    __syncthreads();

    int j = t;
    float aq[8], ak[8], av[8];
    #pragma unroll
    for (int r = 0; r < 8; r++) { aq[r] = 0.f; ak[r] = 0.f; av[r] = 0.f; }

    #pragma unroll 4
    for (int d = 0; d < 256; d++) {
        float wq = Wq[d*256 + j];
        float wk = Wk[d*256 + j];
        float wv = Wv[d*256 + j];
        float4 s0 = *(const float4*)&ssm[d*8];
        float4 s1 = *(const float4*)&ssm[d*8 + 4];
        float4 n0 = *(const float4*)&nsm[d*8];
        float4 n1 = *(const float4*)&nsm[d*8 + 4];
        aq[0] += n0.x*wq; aq[1] += n0.y*wq; aq[2] += n0.z*wq; aq[3] += n0.w*wq;
        aq[4] += n1.x*wq; aq[5] += n1.y*wq; aq[6] += n1.z*wq; aq[7] += n1.w*wq;
        ak[0] += s0.x*wk; ak[1] += s0.y*wk; ak[2] += s0.z*wk; ak[3] += s0.w*wk;
        ak[4] += s1.x*wk; ak[5] += s1.y*wk; ak[6] += s1.z*wk; ak[7] += s1.w*wk;
        av[0] += s0.x*wv; av[1] += s0.y*wv; av[2] += s0.z*wv; av[3] += s0.w*wv;
        av[4] += s1.x*wv; av[5] += s1.y*wv; av[6] += s1.z*wv; av[7] += s1.w*wv;
    }

    int h = j >> 5, dk = j & 31;
    const float inv_sqrt_dk = 0.17677669529663687f;  // 1/sqrt(32)
    float qsv[8];
    #pragma unroll
    for (int r = 0; r < 8; r++) qsv[r] = aq[r] * inv_sqrt_dk;

    #pragma unroll
    for (int r = 0; r < 8; r++) {
        int e = e0 + r;
        if (e < EE) {
            int base = ((b*HH + h)*EE + e)*32 + dk;
            g_q[base] = qsv[r];
            g_k[base] = ak[r];
            g_v[base] = av[r];
        }
    }

    #pragma unroll
    for (int p = 0; p < 6; p++) {
        float rv = rpr[p*32 + lane];
        #pragma unroll
        for (int r = 0; r < 8; r++) {
            float pv = warp_sum(qsv[r] * rv);
            if (lane == 0 && (e0 + r) < EE)
                g_qdr[((b*HH + h)*EE + (e0 + r))*8 + p] = pv;
        }
    }
}

// ---------------- K2: attention ----------------
#define SC_LD 1504
// floats: sc 24064 + qsm 512 + qdr 128 + flag 16
#define SMEM_ATTN ((16*SC_LD + 512 + 128 + 16)*4)

__global__ void __launch_bounds__(512, 1) attn_kernel(
    const int* __restrict__ dist, float* __restrict__ out)
{
    extern __shared__ __align__(16) float sm[];
    float* sc   = sm;                    // 16 x 1504 scores -> attn (normalized)
    float* qsm  = sc + 16*SC_LD;         // 16 x 32 scaled q
    float* qdr  = qsm + 512;             // 16 x 8 bias table
    float* flag = qdr + 128;             // 16 row-valid flags

    int qt = blockIdx.x, h = blockIdx.y, b = blockIdx.z;
    int q0 = qt * 16;
    int t  = threadIdx.x;
    int bh = b*HH + h;
    const float* kbase = g_k + bh*(EE*32);
    const float* vbase = g_v + bh*(EE*32);

    for (int i = t; i < 16*32; i += 512) {
        int qg = q0 + (i >> 5);
        qsm[i] = (qg < EE) ? g_q[(bh*EE + qg)*32 + (i & 31)] : 0.f;
    }
    if (t < 16*8) {
        int qg = q0 + (t >> 3);
        qdr[t] = (qg < EE) ? g_qdr[(bh*EE + qg)*8 + (t & 7)] : 0.f;
    }
    __syncthreads();

    // ================= score phase (barrier-free) =================
    // thread = (kcol = t&127, qgrp = t>>7), rows {qgrp, qgrp+4, qgrp+8, qgrp+12}
    // K column lives in registers (direct LDG); q via broadcast LDS.
    const int* distb = dist + (long long)b*(EE*EE);
    int kcol = t & 127, qgrp = t >> 7;

    const ull* qp0 = (const ull*)(qsm + (qgrp     )*32);
    const ull* qp1 = (const ull*)(qsm + (qgrp +  4)*32);
    const ull* qp2 = (const ull*)(qsm + (qgrp +  8)*32);
    const ull* qp3 = (const ull*)(qsm + (qgrp + 12)*32);
    int qg0 = q0 + qgrp, qg1 = qg0 + 4, qg2 = qg0 + 8, qg3 = qg0 + 12;

    #pragma unroll 1
    for (int c = 0; c < 12; c++) {
        int kc = c * 128;
        int kg = kc + kcol;
        if (kg >= EE) continue;

        // dist first (consumed last -> latency hidden behind K + FMA)
        int dv0 = (qg0 < EE) ? distb[qg0*EE + kg] : 99;
        int dv1 = (qg1 < EE) ? distb[qg1*EE + kg] : 99;
        int dv2 = (qg2 < EE) ? distb[qg2*EE + kg] : 99;
        int dv3 = (qg3 < EE) ? distb[qg3*EE + kg] : 99;

        // K column -> registers (4x LDG.128)
        ull kreg[16];
        {
            const ulonglong2* kp = (const ulonglong2*)(kbase + kg*32);
            #pragma unroll
            for (int j = 0; j < 8; j++) {
                ulonglong2 kv = kp[j];
                kreg[2*j]   = kv.x;
                kreg[2*j+1] = kv.y;
            }
        }

        ull a0 = 0, a1 = 0, a2 = 0, a3 = 0;
        #pragma unroll
        for (int j = 0; j < 16; j++) {
            ull kj = kreg[j];
            fma2(a0, qp0[j], kj);
            fma2(a1, qp1[j], kj);
            fma2(a2, qp2[j], kj);
            fma2(a3, qp3[j], kj);
        }

        float s;
        s = -1e9f; if (dv0 <= 3) s = f2sum(a0) + qdr[(qgrp     )*8 + dv0];
        sc[(qgrp     )*SC_LD + kg] = s;
        s = -1e9f; if (dv1 <= 3) s = f2sum(a1) + qdr[(qgrp +  4)*8 + dv1];
        sc[(qgrp +  4)*SC_LD + kg] = s;
        s = -1e9f; if (dv2 <= 3) s = f2sum(a2) + qdr[(qgrp +  8)*8 + dv2];
        sc[(qgrp +  8)*SC_LD + kg] = s;
        s = -1e9f; if (dv3 <= 3) s = f2sum(a3) + qdr[(qgrp + 12)*8 + dv3];
        sc[(qgrp + 12)*SC_LD + kg] = s;
    }
    __syncthreads();

    // ================= softmax (one row per warp) + attn write =================
    int w = t >> 5, lane = t & 31;
    {
        int rr = w;
        int qg = q0 + rr;
        if (qg < EE) {
            float* row = sc + rr*SC_LD;
            float m = -3.4e38f;
            for (int k = lane*4; k < EE; k += 128) {
                float4 v = *(const float4*)&row[k];
                m = fmaxf(m, fmaxf(fmaxf(v.x, v.y), fmaxf(v.z, v.w)));
            }
            m = warp_max(m);
            float sum = 0.f;
            for (int k = lane*4; k < EE; k += 128) {
                float4 v = *(float4*)&row[k];
                v.x = __expf(v.x - m); v.y = __expf(v.y - m);
                v.z = __expf(v.z - m); v.w = __expf(v.w - m);
                *(float4*)&row[k] = v;
                sum += (v.x + v.y) + (v.z + v.w);
            }
            sum = warp_sum(sum);
            float inv = 1.f / sum;
            if (lane == 0) flag[rr] = (m < -1e8f) ? 0.f : 1.f;
            long long obase = (long long)O_ATTN + (long long)(bh*EE + qg)*EE;
            for (int k = lane*4; k < EE; k += 128) {
                float4 v = *(float4*)&row[k];
                v.x *= inv; v.y *= inv; v.z *= inv; v.w *= inv;
                *(float4*)&out[obase + k] = v;
                *(float4*)&row[k] = v;
            }
        } else {
            if (lane == 0) flag[rr] = 0.f;
        }
    }
    __syncthreads();

    // column sums -> one REDG per column
    for (int k = t; k < EE; k += 512) {
        float s = 0.f;
        #pragma unroll
        for (int r = 0; r < 16; r++) s += sc[r*SC_LD + k] * flag[r];
        atomicAdd(&g_asum[b*EE + k], s);
    }

    // ================= AV (barrier-free; V direct from gmem) =================
    // thread = (lane: 4-k slice) x (dgrp: 8 d) x (qgrp2: 4 q rows)
    int dgrp = (t >> 5) & 3;
    int qgrp2 = t >> 7;
    ull acc[4][4];   // [q-slot][d-pair]  d = 8*dgrp + p*2 + {0,1}
    #pragma unroll
    for (int s = 0; s < 4; s++)
        #pragma unroll
        for (int p = 0; p < 4; p++) acc[s][p] = 0;

    #pragma unroll 1
    for (int c = 0; c < 12; c++) {
        int kc = c * 128, cw = min(128, EE - kc);
        if (4*lane >= cw) continue;   // cw is a multiple of 4

        // attn values: one coalesced LDS128 per q row (4 k values)
        float4 a0 = *(const float4*)&sc[(qgrp2     )*SC_LD + kc + 4*lane];
        float4 a1 = *(const float4*)&sc[(qgrp2 +  4)*SC_LD + kc + 4*lane];
        float4 a2 = *(const float4*)&sc[(qgrp2 +  8)*SC_LD + kc + 4*lane];
        float4 a3 = *(const float4*)&sc[(qgrp2 + 12)*SC_LD + kc + 4*lane];

        #pragma unroll
        for (int kk = 0; kk < 4; kk++) {
            int k = kc + 4*lane + kk;
            const ulonglong2* vp = (const ulonglong2*)(vbase + k*32 + dgrp*8);
            ulonglong2 vv = vp[0];           // d pairs 0,1 of this dgrp
            ull vA0 = vv.x, vA1 = vv.y;
            vv = vp[1];                       // d pairs 2,3
            ull vB0 = vv.x, vB1 = vv.y;

            float f0 = (kk==0)?a0.x:(kk==1)?a0.y:(kk==2)?a0.z:a0.w;
            float f1 = (kk==0)?a1.x:(kk==1)?a1.y:(kk==2)?a1.z:a1.w;
            float f2v = (kk==0)?a2.x:(kk==1)?a2.y:(kk==2)?a2.z:a2.w;
            float f3 = (kk==0)?a3.x:(kk==1)?a3.y:(kk==2)?a3.z:a3.w;
            ull s0 = packf2(f0, f0);
            ull s1 = packf2(f1, f1);
            ull s2 = packf2(f2v, f2v);
            ull s3 = packf2(f3, f3);
            fma2(acc[0][0], s0, vA0); fma2(acc[0][1], s0, vA1);
            fma2(acc[0][2], s0, vB0); fma2(acc[0][3], s0, vB1);
            fma2(acc[1][0], s1, vA0); fma2(acc[1][1], s1, vA1);
            fma2(acc[1][2], s1, vB0); fma2(acc[1][3], s1, vB1);
            fma2(acc[2][0], s2, vA0); fma2(acc[2][1], s2, vA1);
            fma2(acc[2][2], s2, vB0); fma2(acc[2][3], s2, vB1);
            fma2(acc[3][0], s3, vA0); fma2(acc[3][1], s3, vA1);
            fma2(acc[3][2], s3, vB0); fma2(acc[3][3], s3, vB1);
        }
    }

    // reduce the 32 k-slices within each warp (lane = k-slice)
    #pragma unroll
    for (int s = 0; s < 4; s++) {
        #pragma unroll
        for (int p = 0; p < 4; p++) {
            ull a = acc[s][p];
            #pragma unroll
            for (int o = 16; o; o >>= 1)
                a = f2add(a, __shfl_xor_sync(0xffffffffu, a, o));
            acc[s][p] = a;
        }
    }
    if (lane == 0) {
        #pragma unroll
        for (int s = 0; s < 4; s++) {
            int qg = q0 + qgrp2 + 4*s;
            if (qg < EE) {
                ull* op = (ull*)&g_o[(b*EE + qg)*DD + h*32 + 8*dgrp];
                op[0] = acc[s][0]; op[1] = acc[s][1];
                op[2] = acc[s][2]; op[3] = acc[s][3];
            }
        }
    }
}

// ---------------- K3: FC + residual + transpose-out ----------------
__global__ void __launch_bounds__(256) fc_kernel(
    const float* __restrict__ x, const float* __restrict__ Wfc,
    float* __restrict__ out)
{
    __shared__ __align__(16) float osm[256*8];   // [d][r]
    int b  = blockIdx.y;
    int e0 = blockIdx.x * 8;
    int t  = threadIdx.x;

    for (int i = t; i < 2048; i += 256) {
        int r = i >> 8, d = i & 255;
        int e = e0 + r;
        osm[d*8 + r] = (e < EE) ? g_o[(b*EE + e)*DD + d] : 0.f;
    }
    __syncthreads();

    int j = t;
    const float* xb = x + b*DD*EE + j*EE;
    float acc[8];
    #pragma unroll
    for (int r = 0; r < 8; r++) {
        int e = e0 + r;
        acc[r] = (e < EE) ? xb[e] : 0.f;   // residual
    }
    #pragma unroll 4
    for (int d = 0; d < 256; d++) {
        float wv = Wfc[d*256 + j];
        float4 o0 = *(const float4*)&osm[d*8];
        float4 o1 = *(const float4*)&osm[d*8 + 4];
        acc[0] += o0.x*wv; acc[1] += o0.y*wv; acc[2] += o0.z*wv; acc[3] += o0.w*wv;
        acc[4] += o1.x*wv; acc[5] += o1.y*wv; acc[6] += o1.z*wv; acc[7] += o1.w*wv;
    }
    float* ob = out + b*DD*EE + j*EE + e0;
    if (e0 + 8 <= EE) {
        *(float4*)ob       = make_float4(acc[0], acc[1], acc[2], acc[3]);
        *(float4*)(ob + 4) = make_float4(acc[4], acc[5], acc[6], acc[7]);
    } else {
        for (int r = 0; r < 8; r++)
            if (e0 + r < EE) ob[r] = acc[r];
    }
}

// ---------------- K4: attn_per_edge ----------------
__global__ void finalize_kernel(float* __restrict__ out) {
    int i = blockIdx.x * 256 + threadIdx.x;
    if (i < BB*EE) {
        out[O_APE + i] = g_asum[i] / (float)g_acnt[i];
    }
}

// ---------------- launch ----------------
extern "C" void kernel_launch(void* const* d_in, const int* in_sizes, int n_in,
                              void* d_out, int out_size)
{
    const float* x    = (const float*)d_in[0];
    const int*   dist = (const int*)  d_in[1];
    const float* Wq   = (const float*)d_in[2];
    const float* Wk   = (const float*)d_in[3];
    const float* Wv   = (const float*)d_in[4];
    const float* Wfc  = (const float*)d_in[5];
    const float* lnw  = (const float*)d_in[6];
    const float* lnb  = (const float*)d_in[7];
    const float* rpr  = (const float*)d_in[8];
    float* out = (float*)d_out;

    cudaFuncSetAttribute(attn_kernel,
        cudaFuncAttributeMaxDynamicSharedMemorySize, SMEM_ATTN);

    zero_kernel<<<24, 256>>>();

    dim3 gc(24, 8);
    count_kernel<<<gc, 256>>>(dist);

    dim3 g1(188, BB);
    proj_kernel<<<g1, 256>>>(x, Wq, Wk, Wv, lnw, lnb, rpr);

    dim3 g2(94, HH, BB);
    attn_kernel<<<g2, 512, SMEM_ATTN>>>(dist, out);

    dim3 g3(188, BB);
    fc_kernel<<<g3, 256>>>(x, Wfc, out);

    finalize_kernel<<<24, 256>>>(out);
}

// round 6
// speedup vs baseline: 2.0354x; 2.0354x over previous
#include <cuda_runtime.h>

#define BB 4
#define EE 1500
#define DD 256
#define HH 8
#define DK 32

#define O_ATTN 1536000
#define O_APE  73536000

typedef unsigned long long ull;

// ---------------- scratch (no allocation allowed) ----------------
__device__ float g_q[BB*HH*EE*DK];     // scaled q, [b,h,e,dk]
__device__ float g_k[BB*HH*EE*DK];
__device__ float g_v[BB*HH*EE*DK];
__device__ float g_qdr[BB*HH*EE*8];    // q . base_rpr[p], p padded to 8
__device__ float g_o[BB*EE*DD];        // attention output pre-FC, [b,e,h*32+d]
__device__ float g_asum[BB*EE];
__device__ int   g_acnt[BB*EE];

__device__ __forceinline__ float warp_sum(float v) {
    #pragma unroll
    for (int o = 16; o; o >>= 1) v += __shfl_xor_sync(0xffffffffu, v, o);
    return v;
}
__device__ __forceinline__ float warp_max(float v) {
    #pragma unroll
    for (int o = 16; o; o >>= 1) v = fmaxf(v, __shfl_xor_sync(0xffffffffu, v, o));
    return v;
}

// packed f32x2 helpers (sm_100+)
__device__ __forceinline__ void fma2(ull &d, ull a, ull b) {
    asm("fma.rn.f32x2 %0, %1, %2, %0;" : "+l"(d) : "l"(a), "l"(b));
}
__device__ __forceinline__ ull f2add(ull a, ull b) {
    ull d;
    asm("add.rn.f32x2 %0, %1, %2;" : "=l"(d) : "l"(a), "l"(b));
    return d;
}
__device__ __forceinline__ ull f2mul(ull a, ull b) {
    ull d;
    asm("mul.rn.f32x2 %0, %1, %2;" : "=l"(d) : "l"(a), "l"(b));
    return d;
}
__device__ __forceinline__ float f2sum(ull u) {
    float lo, hi;
    asm("mov.b64 {%0,%1}, %2;" : "=f"(lo), "=f"(hi) : "l"(u));
    return lo + hi;
}
__device__ __forceinline__ ull packf2(float x, float y) {
    ull u;
    asm("mov.b64 %0, {%1,%2};" : "=l"(u) : "f"(x), "f"(y));
    return u;
}

// ---------------- K0: zero accumulators ----------------
__global__ void zero_kernel() {
    int i = blockIdx.x * 256 + threadIdx.x;
    if (i < BB*EE) { g_asum[i] = 0.f; g_acnt[i] = 0; }
}

// ---------------- K0b: valid-edge counts from dist ----------------
__global__ void count_kernel(const int* __restrict__ dist) {
    int i = blockIdx.x * 256 + threadIdx.x;   // b*EE + e
    if (i >= BB*EE) return;
    int b = i / EE, e = i - b*EE;
    int q0 = blockIdx.y * 188;
    int q1 = min(EE, q0 + 188);
    const int* dp = dist + (long long)b*EE*EE + e;
    int c = 0;
    #pragma unroll 4
    for (int q = q0; q < q1; q++) c += (dp[q*EE] <= 3) ? 1 : 0;
    atomicAdd(&g_acnt[i], c);
}

// ---------------- K1: layernorm + QKV projections + q.rpr ----------------
__global__ void __launch_bounds__(256) proj_kernel(
    const float* __restrict__ x,
    const float* __restrict__ Wq, const float* __restrict__ Wk,
    const float* __restrict__ Wv,
    const float* __restrict__ lnw, const float* __restrict__ lnb,
    const float* __restrict__ rpr)
{
    __shared__ __align__(16) float ssm[256*8];   // [d][r] raw input rows
    __shared__ __align__(16) float nsm[256*8];   // [d][r] layernormed rows
    int b  = blockIdx.y;
    int e0 = blockIdx.x * 8;
    int t  = threadIdx.x;
    const float* xb = x + b*(DD*EE);

    for (int i = t; i < 2048; i += 256) {
        int d = i >> 3, r = i & 7;
        int e = e0 + r;
        ssm[i] = (e < EE) ? xb[d*EE + e] : 0.f;
    }
    __syncthreads();

    int w = t >> 5, lane = t & 31;
    {   // layernorm of row w (one row per warp)
        float s = 0.f;
        #pragma unroll
        for (int i = 0; i < 8; i++) s += ssm[(lane + 32*i)*8 + w];
        s = warp_sum(s);
        float mu = s * (1.f/256.f);
        float vs = 0.f;
        #pragma unroll
        for (int i = 0; i < 8; i++) {
            float dlt = ssm[(lane + 32*i)*8 + w] - mu;
            vs += dlt*dlt;
        }
        vs = warp_sum(vs);
        float rstd = rsqrtf(vs * (1.f/256.f) + 1e-6f);
        #pragma unroll
        for (int i = 0; i < 8; i++) {
            int d = lane + 32*i;
            nsm[d*8 + w] = (ssm[d*8 + w] - mu) * rstd * lnw[d] + lnb[d];
        }
    }
    __syncthreads();

    int j = t;
    float aq[8], ak[8], av[8];
    #pragma unroll
    for (int r = 0; r < 8; r++) { aq[r] = 0.f; ak[r] = 0.f; av[r] = 0.f; }

    #pragma unroll 4
    for (int d = 0; d < 256; d++) {
        float wq = Wq[d*256 + j];
        float wk = Wk[d*256 + j];
        float wv = Wv[d*256 + j];
        float4 s0 = *(const float4*)&ssm[d*8];
        float4 s1 = *(const float4*)&ssm[d*8 + 4];
        float4 n0 = *(const float4*)&nsm[d*8];
        float4 n1 = *(const float4*)&nsm[d*8 + 4];
        aq[0] += n0.x*wq; aq[1] += n0.y*wq; aq[2] += n0.z*wq; aq[3] += n0.w*wq;
        aq[4] += n1.x*wq; aq[5] += n1.y*wq; aq[6] += n1.z*wq; aq[7] += n1.w*wq;
        ak[0] += s0.x*wk; ak[1] += s0.y*wk; ak[2] += s0.z*wk; ak[3] += s0.w*wk;
        ak[4] += s1.x*wk; ak[5] += s1.y*wk; ak[6] += s1.z*wk; ak[7] += s1.w*wk;
        av[0] += s0.x*wv; av[1] += s0.y*wv; av[2] += s0.z*wv; av[3] += s0.w*wv;
        av[4] += s1.x*wv; av[5] += s1.y*wv; av[6] += s1.z*wv; av[7] += s1.w*wv;
    }

    int h = j >> 5, dk = j & 31;
    const float inv_sqrt_dk = 0.17677669529663687f;  // 1/sqrt(32)
    float qsv[8];
    #pragma unroll
    for (int r = 0; r < 8; r++) qsv[r] = aq[r] * inv_sqrt_dk;

    #pragma unroll
    for (int r = 0; r < 8; r++) {
        int e = e0 + r;
        if (e < EE) {
            int base = ((b*HH + h)*EE + e)*32 + dk;
            g_q[base] = qsv[r];
            g_k[base] = ak[r];
            g_v[base] = av[r];
        }
    }

    #pragma unroll
    for (int p = 0; p < 6; p++) {
        float rv = rpr[p*32 + lane];
        #pragma unroll
        for (int r = 0; r < 8; r++) {
            float pv = warp_sum(qsv[r] * rv);
            if (lane == 0 && (e0 + r) < EE)
                g_qdr[((b*HH + h)*EE + (e0 + r))*8 + p] = pv;
        }
    }
}

// ---------------- K2: attention ----------------
#define SC_LD 1512
// floats: sc 16*1512 + buf0 4096 + buf1 4096 + qsm 512 + qdr 128 + flaginv 16 + invr 16
#define SMEM_ATTN ((16*SC_LD + 4096 + 4096 + 512 + 128 + 16 + 16)*4)

__global__ void __launch_bounds__(512, 1) attn_kernel(
    const int* __restrict__ dist, float* __restrict__ out)
{
    extern __shared__ __align__(16) float sm[];
    float* sc      = sm;                    // 16 x 1512 scores (unnormalized exp)
    float* buf0f   = sc + 16*SC_LD;         // 16KB staging (K_T pairs / V natural)
    float* buf1f   = buf0f + 4096;
    float* qsm     = buf1f + 4096;          // 16 x 32 scaled q
    float* qdr     = qsm + 512;             // 16 x 8 bias table
    float* flaginv = qdr + 128;             // 16: inv (or 0 if fullmask)
    float* invr    = flaginv + 16;          // 16: inv always

    int qt = blockIdx.x, h = blockIdx.y, b = blockIdx.z;
    int q0 = qt * 16;
    int t  = threadIdx.x;
    int bh = b*HH + h;
    const float* kbase = g_k + bh*(EE*32);
    const float* vbase = g_v + bh*(EE*32);

    for (int i = t; i < 16*32; i += 512) {
        int qg = q0 + (i >> 5);
        qsm[i] = (qg < EE) ? g_q[(bh*EE + qg)*32 + (i & 31)] : 0.f;
    }
    if (t < 16*8) {
        int qg = q0 + (t >> 3);
        qdr[t] = (qg < EE) ? g_qdr[(bh*EE + qg)*8 + (t & 7)] : 0.f;
    }
    __syncthreads();

    // ================= score phase =================
    // warp w = t>>5: rg = w&1 (row group of 8), kgp = w>>1 (16-k group)
    // lane: qq = (t>>3)&3, kl = t&7
    // thread cells: rows {r0, r1=r0+4} x cols {kA, kB=kA+8}
    const int* distb = dist + (long long)b*(EE*EE);
    int rg  = (t >> 5) & 1;
    int kgp = t >> 6;
    int qq  = (t >> 3) & 3;
    int kl  = t & 7;
    int r0 = 8*rg + qq, r1 = r0 + 4;
    int kA = kgp*16 + kl, kB = kA + 8;
    int qg0 = q0 + r0, qg1 = q0 + r1;

    // Q rows into registers (broadcast LDS64, once)
    ull qr0[16], qr1[16];
    {
        const ull* a = (const ull*)(qsm + r0*32);
        const ull* bq = (const ull*)(qsm + r1*32);
        #pragma unroll
        for (int j = 0; j < 16; j++) { qr0[j] = a[j]; qr1[j] = bq[j]; }
    }

    // prologue: prefetch chunk 0 (K + dist)
    float4 p0, p1; bool v0, v1;
    int d00, d01, d10, d11;
    {
        v0 = true; v1 = true;
        p0 = *(const float4*)&kbase[t*4];
        p1 = *(const float4*)&kbase[(t + 512)*4];
        d00 = (qg0 < EE) ? distb[qg0*EE + kA] : 99;
        d01 = (qg0 < EE) ? distb[qg0*EE + kB] : 99;
        d10 = (qg1 < EE) ? distb[qg1*EE + kA] : 99;
        d11 = (qg1 < EE) ? distb[qg1*EE + kB] : 99;
    }

    for (int c = 0; c < 12; c++) {
        int kc = c * 128;
        ull* bp = (ull*)((c & 1) ? buf1f : buf0f);
        // stage K_T[j][k^( (j>>1)<<2 )]  (pair-transposed, swizzled)
        if (v0) {
            int kr = t >> 3, ds = t & 7;
            int sw = kr ^ (ds << 2);
            bp[(2*ds    )*128 + sw] = packf2(p0.x, p0.y);
            bp[(2*ds + 1)*128 + sw] = packf2(p0.z, p0.w);
        }
        if (v1) {
            int i = t + 512;
            int kr = i >> 3, ds = i & 7;
            int sw = kr ^ (ds << 2);
            bp[(2*ds    )*128 + sw] = packf2(p1.x, p1.y);
            bp[(2*ds + 1)*128 + sw] = packf2(p1.z, p1.w);
        }
        __syncthreads();

        // prefetch chunk c+1
        float4 n0 = p0, n1 = p1; bool w0 = false, w1 = false;
        int e00 = 99, e01 = 99, e10 = 99, e11 = 99;
        if (c < 11) {
            int kc2 = kc + 128, cw2 = min(128, EE - kc2);
            w0 = (t       < cw2*8);
            w1 = (t + 512 < cw2*8);
            if (w0) n0 = *(const float4*)&kbase[kc2*32 + t*4];
            if (w1) n1 = *(const float4*)&kbase[kc2*32 + (t+512)*4];
            int kg2A = kc2 + kA, kg2B = kc2 + kB;
            if (qg0 < EE && kg2A < EE) e00 = distb[qg0*EE + kg2A];
            if (qg0 < EE && kg2B < EE) e01 = distb[qg0*EE + kg2B];
            if (qg1 < EE && kg2A < EE) e10 = distb[qg1*EE + kg2A];
            if (qg1 < EE && kg2B < EE) e11 = distb[qg1*EE + kg2B];
        }

        // compute 4 cells over 32 d (16 f32x2 pairs)
        ull a00 = 0, a01 = 0, a10 = 0, a11 = 0;
        #pragma unroll
        for (int j = 0; j < 16; j++) {
            int sw = (j >> 1) << 2;
            ull ka = bp[j*128 + (kA ^ sw)];
            ull kb = bp[j*128 + (kB ^ sw)];
            fma2(a00, qr0[j], ka); fma2(a01, qr0[j], kb);
            fma2(a10, qr1[j], ka); fma2(a11, qr1[j], kb);
        }

        // epilogue: bias + mask + store
        int kgA = kc + kA, kgB = kc + kB;
        if (kgA < EE) {
            float s = -1e9f;
            if (d00 <= 3) s = f2sum(a00) + qdr[r0*8 + d00];
            sc[r0*SC_LD + kgA] = s;
            s = -1e9f;
            if (d10 <= 3) s = f2sum(a10) + qdr[r1*8 + d10];
            sc[r1*SC_LD + kgA] = s;
        }
        if (kgB < EE) {
            float s = -1e9f;
            if (d01 <= 3) s = f2sum(a01) + qdr[r0*8 + d01];
            sc[r0*SC_LD + kgB] = s;
            s = -1e9f;
            if (d11 <= 3) s = f2sum(a11) + qdr[r1*8 + d11];
            sc[r1*SC_LD + kgB] = s;
        }

        p0 = n0; p1 = n1; v0 = w0; v1 = w1;
        d00 = e00; d01 = e01; d10 = e10; d11 = e11;
    }
    __syncthreads();

    // prefetch V chunk 0 early (latency hides behind softmax)
    float4 vp0 = *(const float4*)&vbase[t*4];
    float4 vp1 = *(const float4*)&vbase[(t + 512)*4];
    bool vv0 = true, vv1 = true;

    // ===== softmax (one row per warp): exp in place (unnormalized), write attn =====
    int w = t >> 5, lane = t & 31;
    {
        int rr = w;
        int qg = q0 + rr;
        if (qg < EE) {
            float* row = sc + rr*SC_LD;
            float m = -3.4e38f;
            for (int k = lane*4; k < EE; k += 128) {
                float4 v = *(const float4*)&row[k];
                m = fmaxf(m, fmaxf(fmaxf(v.x, v.y), fmaxf(v.z, v.w)));
            }
            m = warp_max(m);
            float sum = 0.f;
            for (int k = lane*4; k < EE; k += 128) {
                float4 v = *(float4*)&row[k];
                v.x = __expf(v.x - m); v.y = __expf(v.y - m);
                v.z = __expf(v.z - m); v.w = __expf(v.w - m);
                *(float4*)&row[k] = v;
                sum += (v.x + v.y) + (v.z + v.w);
            }
            sum = warp_sum(sum);
            float inv = 1.f / sum;
            if (lane == 0) {
                invr[rr] = inv;
                flaginv[rr] = (m < -1e8f) ? 0.f : inv;
            }
            long long obase = (long long)O_ATTN + (long long)(bh*EE + qg)*EE;
            for (int k = lane*4; k < EE; k += 128) {
                float4 v = *(const float4*)&row[k];
                v.x *= inv; v.y *= inv; v.z *= inv; v.w *= inv;
                *(float4*)&out[obase + k] = v;
            }
        } else {
            if (lane == 0) { invr[rr] = 0.f; flaginv[rr] = 0.f; }
        }
    }
    __syncthreads();

    // column sums (on unnormalized exp * flaginv) -> one REDG per column
    for (int k = t; k < EE; k += 512) {
        float s = 0.f;
        #pragma unroll
        for (int r = 0; r < 16; r++) s += sc[r*SC_LD + k] * flaginv[r];
        atomicAdd(&g_asum[b*EE + k], s);
    }

    // ================= AV =================
    // warp w owns in-chunk k range [w*8, w*8+8); lane: qq2 = (t>>3)&3, dp = t&7
    // thread accumulates rows {qq2+4i} x d-pairs {dp, dp+8}  (unnormalized)
    int qq2 = (t >> 3) & 3;
    int dp  = t & 7;
    ull acc[4][2];
    #pragma unroll
    for (int i = 0; i < 4; i++) { acc[i][0] = 0; acc[i][1] = 0; }

    for (int c = 0; c < 12; c++) {
        int kc = c * 128;
        float4* bp4 = (float4*)((c & 1) ? buf1f : buf0f);
        // stage V natural [k][d] (coalesced, conflict-free)
        if (vv0) bp4[t] = vp0;
        if (vv1) bp4[t + 512] = vp1;
        __syncthreads();

        // prefetch next V chunk
        float4 n0 = vp0, n1 = vp1; bool nw0 = false, nw1 = false;
        if (c < 11) {
            int kc2 = kc + 128, cw2 = min(128, EE - kc2);
            nw0 = (t       < cw2*8);
            nw1 = (t + 512 < cw2*8);
            if (nw0) n0 = *(const float4*)&vbase[kc2*32 + t*4];
            if (nw1) n1 = *(const float4*)&vbase[kc2*32 + (t+512)*4];
        }

        const ull* vb = (const ull*)bp4;
        int kb0 = w * 8;
        #pragma unroll
        for (int k4 = 0; k4 < 8; k4 += 4) {
            int kloc = kb0 + k4;
            int kg = kc + kloc;
            if (kg < EE) {   // EE%4==0 so full 4-block valid
                float4 a0 = *(const float4*)&sc[(qq2     )*SC_LD + kg];
                float4 a1 = *(const float4*)&sc[(qq2 +  4)*SC_LD + kg];
                float4 a2 = *(const float4*)&sc[(qq2 +  8)*SC_LD + kg];
                float4 a3 = *(const float4*)&sc[(qq2 + 12)*SC_LD + kg];
                #pragma unroll
                for (int kk = 0; kk < 4; kk++) {
                    ull va = vb[(kloc + kk)*16 + dp];
                    ull vbb = vb[(kloc + kk)*16 + dp + 8];
                    float f0 = (kk==0)?a0.x:(kk==1)?a0.y:(kk==2)?a0.z:a0.w;
                    float f1 = (kk==0)?a1.x:(kk==1)?a1.y:(kk==2)?a1.z:a1.w;
                    float f2 = (kk==0)?a2.x:(kk==1)?a2.y:(kk==2)?a2.z:a2.w;
                    float f3 = (kk==0)?a3.x:(kk==1)?a3.y:(kk==2)?a3.z:a3.w;
                    ull s0 = packf2(f0, f0);
                    ull s1 = packf2(f1, f1);
                    ull s2 = packf2(f2, f2);
                    ull s3 = packf2(f3, f3);
                    fma2(acc[0][0], s0, va); fma2(acc[0][1], s0, vbb);
                    fma2(acc[1][0], s1, va); fma2(acc[1][1], s1, vbb);
                    fma2(acc[2][0], s2, va); fma2(acc[2][1], s2, vbb);
                    fma2(acc[3][0], s3, va); fma2(acc[3][1], s3, vbb);
                }
            }
        }
        vp0 = n0; vp1 = n1; vv0 = nw0; vv1 = nw1;
    }

    // cross-warp k-reduction via smem partials (sc region is free now)
    __syncthreads();          // all AV reads of sc done
    {
        ull* part = (ull*)sm;  // [w][row][pair] : 16 x 16 x 16 ull
        #pragma unroll
        for (int i = 0; i < 4; i++) {
            int r = qq2 + 4*i;
            part[w*256 + r*16 + dp]     = acc[i][0];
            part[w*256 + r*16 + dp + 8] = acc[i][1];
        }
    }
    __syncthreads();
    if (t < 256) {
        const ull* part = (const ull*)sm;
        ull s = 0;
        #pragma unroll
        for (int ww = 0; ww < 16; ww++) s = f2add(s, part[ww*256 + t]);
        int row = t >> 4, p = t & 15;
        int qg = q0 + row;
        if (qg < EE) {
            float iv = invr[row];
            ull r = f2mul(s, packf2(iv, iv));
            *(ull*)&g_o[(b*EE + qg)*DD + h*32 + 2*p] = r;
        }
    }
}

// ---------------- K3: FC + residual + transpose-out ----------------
__global__ void __launch_bounds__(256) fc_kernel(
    const float* __restrict__ x, const float* __restrict__ Wfc,
    float* __restrict__ out)
{
    __shared__ __align__(16) float osm[256*8];   // [d][r]
    int b  = blockIdx.y;
    int e0 = blockIdx.x * 8;
    int t  = threadIdx.x;

    for (int i = t; i < 2048; i += 256) {
        int r = i >> 8, d = i & 255;
        int e = e0 + r;
        osm[d*8 + r] = (e < EE) ? g_o[(b*EE + e)*DD + d] : 0.f;
    }
    __syncthreads();

    int j = t;
    const float* xb = x + b*DD*EE + j*EE;
    float acc[8];
    #pragma unroll
    for (int r = 0; r < 8; r++) {
        int e = e0 + r;
        acc[r] = (e < EE) ? xb[e] : 0.f;   // residual
    }
    #pragma unroll 4
    for (int d = 0; d < 256; d++) {
        float wv = Wfc[d*256 + j];
        float4 o0 = *(const float4*)&osm[d*8];
        float4 o1 = *(const float4*)&osm[d*8 + 4];
        acc[0] += o0.x*wv; acc[1] += o0.y*wv; acc[2] += o0.z*wv; acc[3] += o0.w*wv;
        acc[4] += o1.x*wv; acc[5] += o1.y*wv; acc[6] += o1.z*wv; acc[7] += o1.w*wv;
    }
    float* ob = out + b*DD*EE + j*EE + e0;
    if (e0 + 8 <= EE) {
        *(float4*)ob       = make_float4(acc[0], acc[1], acc[2], acc[3]);
        *(float4*)(ob + 4) = make_float4(acc[4], acc[5], acc[6], acc[7]);
    } else {
        for (int r = 0; r < 8; r++)
            if (e0 + r < EE) ob[r] = acc[r];
    }
}

// ---------------- K4: attn_per_edge ----------------
__global__ void finalize_kernel(float* __restrict__ out) {
    int i = blockIdx.x * 256 + threadIdx.x;
    if (i < BB*EE) {
        out[O_APE + i] = g_asum[i] / (float)g_acnt[i];
    }
}

// ---------------- launch ----------------
extern "C" void kernel_launch(void* const* d_in, const int* in_sizes, int n_in,
                              void* d_out, int out_size)
{
    const float* x    = (const float*)d_in[0];
    const int*   dist = (const int*)  d_in[1];
    const float* Wq   = (const float*)d_in[2];
    const float* Wk   = (const float*)d_in[3];
    const float* Wv   = (const float*)d_in[4];
    const float* Wfc  = (const float*)d_in[5];
    const float* lnw  = (const float*)d_in[6];
    const float* lnb  = (const float*)d_in[7];
    const float* rpr  = (const float*)d_in[8];
    float* out = (float*)d_out;

    cudaFuncSetAttribute(attn_kernel,
        cudaFuncAttributeMaxDynamicSharedMemorySize, SMEM_ATTN);

    zero_kernel<<<24, 256>>>();

    dim3 gc(24, 8);
    count_kernel<<<gc, 256>>>(dist);

    dim3 g1(188, BB);
    proj_kernel<<<g1, 256>>>(x, Wq, Wk, Wv, lnw, lnb, rpr);

    dim3 g2(94, HH, BB);
    attn_kernel<<<g2, 512, SMEM_ATTN>>>(dist, out);

    dim3 g3(188, BB);
    fc_kernel<<<g3, 256>>>(x, Wfc, out);

    finalize_kernel<<<24, 256>>>(out);
}

// round 7
// speedup vs baseline: 2.2294x; 1.0953x over previous
#include <cuda_runtime.h>

#define BB 4
#define EE 1500
#define DD 256
#define HH 8
#define DK 32

#define O_ATTN 1536000
#define O_APE  73536000

typedef unsigned long long ull;

// ---------------- scratch (no allocation allowed) ----------------
__device__ float g_q[BB*HH*EE*DK];          // scaled q, [b,h,e,dk]
__device__ ulonglong2 g_k2[BB*HH*16*768];   // K pair-transposed: [bh][j][p] = {k=2p, k=2p+1} d-pair j
__device__ float g_v[BB*HH*EE*DK];
__device__ float g_qdr[BB*HH*EE*8];         // q . base_rpr[p], p padded to 8
__device__ float g_o[BB*EE*DD];             // attention output pre-FC, [b,e,h*32+d]
__device__ float g_asum[BB*EE];
__device__ int   g_acnt[BB*EE];

__device__ __forceinline__ float warp_sum(float v) {
    #pragma unroll
    for (int o = 16; o; o >>= 1) v += __shfl_xor_sync(0xffffffffu, v, o);
    return v;
}

// packed f32x2 helpers (sm_100+)
__device__ __forceinline__ void fma2(ull &d, ull a, ull b) {
    asm("fma.rn.f32x2 %0, %1, %2, %0;" : "+l"(d) : "l"(a), "l"(b));
}
__device__ __forceinline__ ull f2add(ull a, ull b) {
    ull d;
    asm("add.rn.f32x2 %0, %1, %2;" : "=l"(d) : "l"(a), "l"(b));
    return d;
}
__device__ __forceinline__ ull f2mul(ull a, ull b) {
    ull d;
    asm("mul.rn.f32x2 %0, %1, %2;" : "=l"(d) : "l"(a), "l"(b));
    return d;
}
__device__ __forceinline__ float f2sum(ull u) {
    float lo, hi;
    asm("mov.b64 {%0,%1}, %2;" : "=f"(lo), "=f"(hi) : "l"(u));
    return lo + hi;
}
__device__ __forceinline__ ull packf2(float x, float y) {
    ull u;
    asm("mov.b64 %0, {%1,%2};" : "=l"(u) : "f"(x), "f"(y));
    return u;
}

// ---------------- K0: zero accumulators ----------------
__global__ void zero_kernel() {
    int i = blockIdx.x * 256 + threadIdx.x;
    if (i < BB*EE) { g_asum[i] = 0.f; g_acnt[i] = 0; }
}

// ---------------- K0b: valid-edge counts from dist ----------------
__global__ void count_kernel(const int* __restrict__ dist) {
    int i = blockIdx.x * 256 + threadIdx.x;   // b*EE + e
    if (i >= BB*EE) return;
    int b = i / EE, e = i - b*EE;
    int q0 = blockIdx.y * 188;
    int q1 = min(EE, q0 + 188);
    const int* dp = dist + (long long)b*EE*EE + e;
    int c = 0;
    #pragma unroll 4
    for (int q = q0; q < q1; q++) c += (dp[q*EE] <= 3) ? 1 : 0;
    atomicAdd(&g_acnt[i], c);
}

// ---------------- K1: layernorm + QKV projections + q.rpr + K pair-transpose ----------------
__global__ void __launch_bounds__(256) proj_kernel(
    const float* __restrict__ x,
    const float* __restrict__ Wq, const float* __restrict__ Wk,
    const float* __restrict__ Wv,
    const float* __restrict__ lnw, const float* __restrict__ lnb,
    const float* __restrict__ rpr)
{
    __shared__ __align__(16) float ssm[256*8];   // [d][r] raw input rows -> later K transpose buffer
    __shared__ __align__(16) float nsm[256*8];   // [d][r] layernormed rows
    int b  = blockIdx.y;
    int e0 = blockIdx.x * 8;
    int t  = threadIdx.x;
    const float* xb = x + b*(DD*EE);

    for (int i = t; i < 2048; i += 256) {
        int d = i >> 3, r = i & 7;
        int e = e0 + r;
        ssm[i] = (e < EE) ? xb[d*EE + e] : 0.f;
    }
    __syncthreads();

    int w = t >> 5, lane = t & 31;
    {   // layernorm of row w (one row per warp)
        float s = 0.f;
        #pragma unroll
        for (int i = 0; i < 8; i++) s += ssm[(lane + 32*i)*8 + w];
        s = warp_sum(s);
        float mu = s * (1.f/256.f);
        float vs = 0.f;
        #pragma unroll
        for (int i = 0; i < 8; i++) {
            float dlt = ssm[(lane + 32*i)*8 + w] - mu;
            vs += dlt*dlt;
        }
        vs = warp_sum(vs);
        float rstd = rsqrtf(vs * (1.f/256.f) + 1e-6f);
        #pragma unroll
        for (int i = 0; i < 8; i++) {
            int d = lane + 32*i;
            nsm[d*8 + w] = (ssm[d*8 + w] - mu) * rstd * lnw[d] + lnb[d];
        }
    }
    __syncthreads();

    int j = t;
    float aq[8], ak[8], av[8];
    #pragma unroll
    for (int r = 0; r < 8; r++) { aq[r] = 0.f; ak[r] = 0.f; av[r] = 0.f; }

    #pragma unroll 4
    for (int d = 0; d < 256; d++) {
        float wq = Wq[d*256 + j];
        float wk = Wk[d*256 + j];
        float wv = Wv[d*256 + j];
        float4 s0 = *(const float4*)&ssm[d*8];
        float4 s1 = *(const float4*)&ssm[d*8 + 4];
        float4 n0 = *(const float4*)&nsm[d*8];
        float4 n1 = *(const float4*)&nsm[d*8 + 4];
        aq[0] += n0.x*wq; aq[1] += n0.y*wq; aq[2] += n0.z*wq; aq[3] += n0.w*wq;
        aq[4] += n1.x*wq; aq[5] += n1.y*wq; aq[6] += n1.z*wq; aq[7] += n1.w*wq;
        ak[0] += s0.x*wk; ak[1] += s0.y*wk; ak[2] += s0.z*wk; ak[3] += s0.w*wk;
        ak[4] += s1.x*wk; ak[5] += s1.y*wk; ak[6] += s1.z*wk; ak[7] += s1.w*wk;
        av[0] += s0.x*wv; av[1] += s0.y*wv; av[2] += s0.z*wv; av[3] += s0.w*wv;
        av[4] += s1.x*wv; av[5] += s1.y*wv; av[6] += s1.z*wv; av[7] += s1.w*wv;
    }

    int h = j >> 5, dk = j & 31;
    const float inv_sqrt_dk = 0.17677669529663687f;  // 1/sqrt(32)
    float qsv[8];
    #pragma unroll
    for (int r = 0; r < 8; r++) qsv[r] = aq[r] * inv_sqrt_dk;

    #pragma unroll
    for (int r = 0; r < 8; r++) {
        int e = e0 + r;
        if (e < EE) {
            int base = ((b*HH + h)*EE + e)*32 + dk;
            g_q[base] = qsv[r];
            g_v[base] = av[r];
        }
    }

    #pragma unroll
    for (int p = 0; p < 6; p++) {
        float rv = rpr[p*32 + lane];
        #pragma unroll
        for (int r = 0; r < 8; r++) {
            float pv = warp_sum(qsv[r] * rv);
            if (lane == 0 && (e0 + r) < EE)
                g_qdr[((b*HH + h)*EE + (e0 + r))*8 + p] = pv;
        }
    }

    // ---- K pair-transpose: g_k2[bh][j][p] = {pack(K[2p][2j],K[2p][2j+1]), same for k=2p+1} ----
    __syncthreads();                     // all ssm/nsm reads done
    #pragma unroll
    for (int r = 0; r < 8; r++) ssm[t*8 + r] = ak[r];   // ssm[(h*32+dk)][r]
    __syncthreads();
    {
        int hh = t >> 5;                 // 0..7
        int jj = (t >> 1) & 15;          // 0..15 d-pair
        int ph = t & 1;                  // which half of the 4 pairs
        const float* s0 = &ssm[(hh*32 + 2*jj    )*8];
        const float* s1 = &ssm[(hh*32 + 2*jj + 1)*8];
        long long base = ((long long)(b*HH + hh)*16 + jj)*768 + (e0 >> 1) + 2*ph;
        #pragma unroll
        for (int ps = 0; ps < 2; ps++) {
            int ee = 4*ph + 2*ps;        // local e of k=2p
            ulonglong2 val;
            val.x = packf2(s0[ee],   s1[ee]);
            val.y = packf2(s0[ee+1], s1[ee+1]);
            g_k2[base + ps] = val;
        }
    }
}

// ---------------- K2: attention ----------------
#define SC_LD 1512
// floats: sc 16*1512 + buf0 4096 + buf1 4096 + qsm 512 + qdr 128 + flaginv 16 + invr 16
#define SMEM_ATTN ((16*SC_LD + 4096 + 4096 + 512 + 128 + 16 + 16)*4)

__global__ void __launch_bounds__(512, 1) attn_kernel(
    const int* __restrict__ dist, float* __restrict__ out)
{
    extern __shared__ __align__(16) float sm[];
    float* sc      = sm;                    // 16 x 1512 scores (unnormalized exp)
    float* buf0f   = sc + 16*SC_LD;         // 16KB staging (K_T ull2 / V natural)
    float* buf1f   = buf0f + 4096;
    float* qsm     = buf1f + 4096;          // 16 x 32 scaled q
    float* qdr     = qsm + 512;             // 16 x 8 bias table
    float* flaginv = qdr + 128;             // 16: inv (or 0 if fullmask)
    float* invr    = flaginv + 16;          // 16: inv always

    int qt = blockIdx.x, h = blockIdx.y, b = blockIdx.z;
    int q0 = qt * 16;
    int t  = threadIdx.x;
    int bh = b*HH + h;
    const ulonglong2* k2base = g_k2 + (long long)bh*16*768;
    const float* vbase = g_v + bh*(EE*32);

    for (int i = t; i < 16*32; i += 512) {
        int qg = q0 + (i >> 5);
        qsm[i] = (qg < EE) ? g_q[(bh*EE + qg)*32 + (i & 31)] : 0.f;
    }
    if (t < 16*8) {
        int qg = q0 + (t >> 3);
        qdr[t] = (qg < EE) ? g_qdr[(bh*EE + qg)*8 + (t & 7)] : 0.f;
    }
    __syncthreads();

    // ================= score phase =================
    // warp w: rg = w&1 (row half), kgp = w>>1 (8-pair group)
    // lane: qq = (t>>3)&3, kl = t&7 ; pair p0i = kgp*8+kl -> k cols {2p, 2p+1}
    // thread cells: rows {r0, r1=r0+4} x k {2p0i, 2p0i+1}
    const int* distb = dist + (long long)b*(EE*EE);
    int rg  = (t >> 5) & 1;
    int kgp = t >> 6;
    int qq  = (t >> 3) & 3;
    int r0 = 8*rg + qq, r1 = r0 + 4;
    int p0i = kgp*8 + (t & 7);
    int qg0 = q0 + r0, qg1 = q0 + r1;

    // Q rows into registers (broadcast LDS, once)
    ull qr0[16], qr1[16];
    {
        const ull* a = (const ull*)(qsm + r0*32);
        const ull* bq = (const ull*)(qsm + r1*32);
        #pragma unroll
        for (int jj = 0; jj < 16; jj++) { qr0[jj] = a[jj]; qr1[jj] = bq[jj]; }
    }

    // staging coords: warp = j row, lane = pair offset
    int jst = t >> 5, lst = t & 31;

    // prologue: prefetch chunk 0 (K pairs + dist int2)
    ulonglong2 ps0, ps1;
    int2 dA, dB;
    {
        ps0 = k2base[jst*768 + lst];
        ps1 = k2base[jst*768 + lst + 32];
        int kgA = 2*p0i;
        dA = (qg0 < EE) ? *(const int2*)(distb + (long long)qg0*EE + kgA) : make_int2(99, 99);
        dB = (qg1 < EE) ? *(const int2*)(distb + (long long)qg1*EE + kgA) : make_int2(99, 99);
    }

    for (int c = 0; c < 12; c++) {
        int kc = c * 128;
        ulonglong2* bp = (ulonglong2*)((c & 1) ? buf1f : buf0f);
        // stage K_T chunk: [j][p] ull2, contiguous (no swizzle needed)
        bp[jst*64 + lst]      = ps0;
        bp[jst*64 + lst + 32] = ps1;
        __syncthreads();

        // prefetch chunk c+1
        int2 eA = make_int2(99, 99), eB = make_int2(99, 99);
        if (c < 11) {
            int pc2 = (c + 1)*64;
            ps0 = k2base[jst*768 + pc2 + lst];
            ps1 = k2base[jst*768 + pc2 + lst + 32];
            int kg2 = kc + 128 + 2*p0i;
            if (kg2 < EE) {
                if (qg0 < EE) eA = *(const int2*)(distb + (long long)qg0*EE + kg2);
                if (qg1 < EE) eB = *(const int2*)(distb + (long long)qg1*EE + kg2);
            }
        }

        // compute: 16 LDS128, 64 fma2
        const ulonglong2* prow = bp + p0i;
        ull a00 = 0, a01 = 0, a10 = 0, a11 = 0;
        #pragma unroll
        for (int jj = 0; jj < 16; jj++) {
            ulonglong2 kv = prow[jj*64];
            fma2(a00, qr0[jj], kv.x); fma2(a01, qr0[jj], kv.y);
            fma2(a10, qr1[jj], kv.x); fma2(a11, qr1[jj], kv.y);
        }

        // epilogue: bias + mask + paired store
        int kgA = kc + 2*p0i;
        if (kgA < EE) {
            float sa = -1e9f, sb = -1e9f;
            if (dA.x <= 3) sa = f2sum(a00) + qdr[r0*8 + dA.x];
            if (dA.y <= 3) sb = f2sum(a01) + qdr[r0*8 + dA.y];
            *(ull*)&sc[r0*SC_LD + kgA] = packf2(sa, sb);
            sa = -1e9f; sb = -1e9f;
            if (dB.x <= 3) sa = f2sum(a10) + qdr[r1*8 + dB.x];
            if (dB.y <= 3) sb = f2sum(a11) + qdr[r1*8 + dB.y];
            *(ull*)&sc[r1*SC_LD + kgA] = packf2(sa, sb);
        }
        dA = eA; dB = eB;
    }
    __syncthreads();

    // prefetch V chunk 0 early (latency hides behind softmax)
    float4 vp0 = *(const float4*)&vbase[t*4];
    float4 vp1 = *(const float4*)&vbase[(t + 512)*4];
    bool vv0 = true, vv1 = true;

    // ===== softmax, 2-pass (no max subtraction; masked -1e9 underflows to 0) =====
    int w = t >> 5, lane = t & 31;
    {
        int rr = w;
        int qg = q0 + rr;
        if (qg < EE) {
            float* row = sc + rr*SC_LD;
            float sum = 0.f;
            for (int k = lane*4; k < EE; k += 128) {
                float4 v = *(float4*)&row[k];
                v.x = __expf(v.x); v.y = __expf(v.y);
                v.z = __expf(v.z); v.w = __expf(v.w);
                *(float4*)&row[k] = v;
                sum += (v.x + v.y) + (v.z + v.w);
            }
            sum = warp_sum(sum);
            bool fullmask = (sum == 0.f);
            if (fullmask) {   // reference: softmax of all -1e9 -> uniform
                for (int k = lane*4; k < EE; k += 128)
                    *(float4*)&row[k] = make_float4(1.f, 1.f, 1.f, 1.f);
                sum = (float)EE;
            }
            float inv = 1.f / sum;
            if (lane == 0) {
                invr[rr] = inv;
                flaginv[rr] = fullmask ? 0.f : inv;
            }
            long long obase = (long long)O_ATTN + (long long)(bh*EE + qg)*EE;
            for (int k = lane*4; k < EE; k += 128) {
                float4 v = *(const float4*)&row[k];
                v.x *= inv; v.y *= inv; v.z *= inv; v.w *= inv;
                *(float4*)&out[obase + k] = v;
            }
        } else {
            if (lane == 0) { invr[rr] = 0.f; flaginv[rr] = 0.f; }
        }
    }
    __syncthreads();

    // column sums (unnormalized exp * flaginv) -> one REDG per column
    for (int k = t; k < EE; k += 512) {
        float s = 0.f;
        #pragma unroll
        for (int r = 0; r < 16; r++) s += sc[r*SC_LD + k] * flaginv[r];
        atomicAdd(&g_asum[b*EE + k], s);
    }

    // ================= AV =================
    // warp w owns in-chunk k range [w*8, w*8+8)
    // lane: qq2 = (t>>3)&3 (4 q-rows), dp = t&7 (float4 of d)
    int qq2 = (t >> 3) & 3;
    int dp  = t & 7;
    ull accA[4], accB[4];
    #pragma unroll
    for (int i = 0; i < 4; i++) { accA[i] = 0; accB[i] = 0; }

    for (int c = 0; c < 12; c++) {
        int kc = c * 128;
        float4* bp4 = (float4*)((c & 1) ? buf1f : buf0f);
        if (vv0) bp4[t] = vp0;
        if (vv1) bp4[t + 512] = vp1;
        __syncthreads();

        // prefetch next V chunk
        float4 n0 = vp0, n1 = vp1; bool nw0 = false, nw1 = false;
        if (c < 11) {
            int kc2 = kc + 128, cw2 = min(128, EE - kc2);
            nw0 = (t       < cw2*8);
            nw1 = (t + 512 < cw2*8);
            if (nw0) n0 = *(const float4*)&vbase[kc2*32 + t*4];
            if (nw1) n1 = *(const float4*)&vbase[kc2*32 + (t+512)*4];
        }

        int kb0 = w * 8;
        #pragma unroll
        for (int k4 = 0; k4 < 8; k4 += 4) {
            int kg = kc + kb0 + k4;
            if (kg < EE) {
                float4 a0 = *(const float4*)&sc[(qq2     )*SC_LD + kg];
                float4 a1 = *(const float4*)&sc[(qq2 +  4)*SC_LD + kg];
                float4 a2 = *(const float4*)&sc[(qq2 +  8)*SC_LD + kg];
                float4 a3 = *(const float4*)&sc[(qq2 + 12)*SC_LD + kg];
                #pragma unroll
                for (int kk = 0; kk < 4; kk++) {
                    float4 vv = bp4[(kb0 + k4 + kk)*8 + dp];
                    ull v0 = packf2(vv.x, vv.y), v1 = packf2(vv.z, vv.w);
                    float f0 = (kk==0)?a0.x:(kk==1)?a0.y:(kk==2)?a0.z:a0.w;
                    float f1 = (kk==0)?a1.x:(kk==1)?a1.y:(kk==2)?a1.z:a1.w;
                    float f2 = (kk==0)?a2.x:(kk==1)?a2.y:(kk==2)?a2.z:a2.w;
                    float f3 = (kk==0)?a3.x:(kk==1)?a3.y:(kk==2)?a3.z:a3.w;
                    ull s0 = packf2(f0, f0);
                    ull s1 = packf2(f1, f1);
                    ull s2 = packf2(f2, f2);
                    ull s3 = packf2(f3, f3);
                    fma2(accA[0], s0, v0); fma2(accB[0], s0, v1);
                    fma2(accA[1], s1, v0); fma2(accB[1], s1, v1);
                    fma2(accA[2], s2, v0); fma2(accB[2], s2, v1);
                    fma2(accA[3], s3, v0); fma2(accB[3], s3, v1);
                }
            }
        }
        vp0 = n0; vp1 = n1; vv0 = nw0; vv1 = nw1;
    }

    // cross-warp k-reduction via smem partials (sc region is free now)
    __syncthreads();          // all AV reads of sc done
    {
        ulonglong2* part = (ulonglong2*)sm;   // [w][row][dp] : 16*16*8 ull2 = 32 KB
        #pragma unroll
        for (int i = 0; i < 4; i++) {
            ulonglong2 v; v.x = accA[i]; v.y = accB[i];
            part[(w*16 + (qq2 + 4*i))*8 + dp] = v;
        }
    }
    __syncthreads();
    if (t < 128) {
        const ulonglong2* part = (const ulonglong2*)sm;
        int row = t >> 3, dpp = t & 7;
        ull sA = 0, sB = 0;
        #pragma unroll
        for (int ww = 0; ww < 16; ww++) {
            ulonglong2 v = part[(ww*16 + row)*8 + dpp];
            sA = f2add(sA, v.x);
            sB = f2add(sB, v.y);
        }
        int qg = q0 + row;
        if (qg < EE) {
            float iv = invr[row];
            ull ivp = packf2(iv, iv);
            ulonglong2 o;
            o.x = f2mul(sA, ivp);
            o.y = f2mul(sB, ivp);
            *(ulonglong2*)&g_o[(b*EE + qg)*DD + h*32 + 4*dpp] = o;
        }
    }
}

// ---------------- K3: FC + residual + transpose-out ----------------
__global__ void __launch_bounds__(256) fc_kernel(
    const float* __restrict__ x, const float* __restrict__ Wfc,
    float* __restrict__ out)
{
    __shared__ __align__(16) float osm[256*8];   // [d][r]
    int b  = blockIdx.y;
    int e0 = blockIdx.x * 8;
    int t  = threadIdx.x;

    for (int i = t; i < 2048; i += 256) {
        int r = i >> 8, d = i & 255;
        int e = e0 + r;
        osm[d*8 + r] = (e < EE) ? g_o[(b*EE + e)*DD + d] : 0.f;
    }
    __syncthreads();

    int j = t;
    const float* xb = x + b*DD*EE + j*EE;
    float acc[8];
    #pragma unroll
    for (int r = 0; r < 8; r++) {
        int e = e0 + r;
        acc[r] = (e < EE) ? xb[e] : 0.f;   // residual
    }
    #pragma unroll 4
    for (int d = 0; d < 256; d++) {
        float wv = Wfc[d*256 + j];
        float4 o0 = *(const float4*)&osm[d*8];
        float4 o1 = *(const float4*)&osm[d*8 + 4];
        acc[0] += o0.x*wv; acc[1] += o0.y*wv; acc[2] += o0.z*wv; acc[3] += o0.w*wv;
        acc[4] += o1.x*wv; acc[5] += o1.y*wv; acc[6] += o1.z*wv; acc[7] += o1.w*wv;
    }
    float* ob = out + b*DD*EE + j*EE + e0;
    if (e0 + 8 <= EE) {
        *(float4*)ob       = make_float4(acc[0], acc[1], acc[2], acc[3]);
        *(float4*)(ob + 4) = make_float4(acc[4], acc[5], acc[6], acc[7]);
    } else {
        for (int r = 0; r < 8; r++)
            if (e0 + r < EE) ob[r] = acc[r];
    }
}

// ---------------- K4: attn_per_edge ----------------
__global__ void finalize_kernel(float* __restrict__ out) {
    int i = blockIdx.x * 256 + threadIdx.x;
    if (i < BB*EE) {
        out[O_APE + i] = g_asum[i] / (float)g_acnt[i];
    }
}

// ---------------- launch ----------------
extern "C" void kernel_launch(void* const* d_in, const int* in_sizes, int n_in,
                              void* d_out, int out_size)
{
    const float* x    = (const float*)d_in[0];
    const int*   dist = (const int*)  d_in[1];
    const float* Wq   = (const float*)d_in[2];
    const float* Wk   = (const float*)d_in[3];
    const float* Wv   = (const float*)d_in[4];
    const float* Wfc  = (const float*)d_in[5];
    const float* lnw  = (const float*)d_in[6];
    const float* lnb  = (const float*)d_in[7];
    const float* rpr  = (const float*)d_in[8];
    float* out = (float*)d_out;

    cudaFuncSetAttribute(attn_kernel,
        cudaFuncAttributeMaxDynamicSharedMemorySize, SMEM_ATTN);

    zero_kernel<<<24, 256>>>();

    dim3 gc(24, 8);
    count_kernel<<<gc, 256>>>(dist);

    dim3 g1(188, BB);
    proj_kernel<<<g1, 256>>>(x, Wq, Wk, Wv, lnw, lnb, rpr);

    dim3 g2(94, HH, BB);
    attn_kernel<<<g2, 512, SMEM_ATTN>>>(dist, out);

    dim3 g3(188, BB);
    fc_kernel<<<g3, 256>>>(x, Wfc, out);

    finalize_kernel<<<24, 256>>>(out);
}